// round 7
// baseline (speedup 1.0000x reference)
#include <cuda_runtime.h>

#define Bn 16
#define Nn 1024
#define Dn 8
#define Cn 128
#define Hn 256
#define NCOND 3
#define MAXIT 4
#define NROWS (Bn * Nn)
#define GRID 128
#define TPB 1024
#define FLT_BIG 3.402823466e38f

// ---------------- device scratch (no allocations allowed) ----------------
__device__ __align__(16) float g_x0[NROWS * Dn];   // 512 KB
__device__ float g_cc[Bn * Hn];
__device__ int g_cnt[MAXIT + 1][Bn];               // per-(pass, batch) masked count
__device__ int g_lists[2][Bn][Nn];                 // ping-pong per-batch masked row lists
__device__ float g_partial[GRID];
__device__ unsigned int g_barc[8];                 // monotonic barrier counters (never reset)

// Software grid barrier. GRID=128 blocks <= 148 SMs at occupancy 1 -> all
// co-resident; monotonic counters need no reset and are replay-deterministic.
__device__ __forceinline__ void gbar(int i) {
    __threadfence();
    __syncthreads();
    if (threadIdx.x == 0) {
        unsigned int old = atomicAdd(&g_barc[i], 1u);
        unsigned int target = (old & ~(unsigned int)(GRID - 1)) + (unsigned int)GRID;
        while (atomicAdd(&g_barc[i], 0u) < target) { __nanosleep(32); }
        __threadfence();
    }
    __syncthreads();
}

// squared distance, sequential d0..d7 accumulation (reference reduction order)
__device__ __forceinline__ float dist8(const float4 xa, const float4 xb,
                                       const float4 da, const float4 db) {
    float t0 = xa.x - da.x; float acc = t0 * t0;
    t0 = xa.y - da.y; acc = fmaf(t0, t0, acc);
    t0 = xa.z - da.z; acc = fmaf(t0, t0, acc);
    t0 = xa.w - da.w; acc = fmaf(t0, t0, acc);
    t0 = xb.x - db.x; acc = fmaf(t0, t0, acc);
    t0 = xb.y - db.y; acc = fmaf(t0, t0, acc);
    t0 = xb.z - db.z; acc = fmaf(t0, t0, acc);
    t0 = xb.w - db.w; acc = fmaf(t0, t0, acc);
    return acc;
}

// smem float4 index for data row m (pad 1 float4 per 64 rows -> conflict-free
// LDS.128 phase-octets: lane octet hits bank-quads 4*s mod 32, all distinct)
#define SIDX(m) (2 * (m) + ((m) >> 6))

__global__ void __launch_bounds__(TPB, 1) k_fused(
    const float* __restrict__ data, const float* __restrict__ c,
    const float* __restrict__ tv,   const float* __restrict__ x0_noise,
    const float* __restrict__ noise_bank,
    const float* __restrict__ W1,   const float* __restrict__ Wc,
    const float* __restrict__ Wt,   const float* __restrict__ b1,
    const float* __restrict__ W2,   float* __restrict__ out) {

    // 33 KB tile (persists through phases 1-2), aliased by weights in phase 3
    __shared__ __align__(16) float smem_raw[(Nn * 2 + 16) * 4];
    __shared__ float swarp[32];
    float4* sdata = (float4*)smem_raw;
    float*  sW1   = smem_raw;
    float*  sW2   = smem_raw + Dn * Hn;
    float*  sbase = smem_raw + 2 * Dn * Hn;

    const int t   = threadIdx.x;
    const int bid = blockIdx.x;
    const int gid = bid * TPB + t;
    const int b    = bid >> 3;           // batch owned by this block
    const int tile = bid & 7;

    // ---------------- phase 0: zero counters, init x0, cc = c @ Wc --------
    if (gid < (MAXIT + 1) * Bn) ((int*)g_cnt)[gid] = 0;
    {
        int i = gid;                      // GRID*TPB == NROWS*Dn exactly
        int d = i & (Dn - 1);
        g_x0[i] = (d < NCOND) ? data[i] : x0_noise[i];
    }
    if (gid < Bn * Hn) {
        int bb = gid >> 8, h = gid & (Hn - 1);
        float acc = 0.f;
        #pragma unroll 8
        for (int j = 0; j < Cn; j++)
            acc = fmaf(c[bb * Cn + j], Wc[j * Hn + h], acc);
        g_cc[gid] = acc;
    }

    // ---------------- load data[b] tile into smem (padded) ----------------
    {
        const float4* dptr = (const float4*)(data + (size_t)b * Nn * Dn);
        for (int i = t; i < Nn * 2; i += TPB) {
            int m = i >> 1;
            sdata[SIDX(m) + (i & 1)] = dptr[i];
        }
    }
    gbar(0);   // also orders smem tile via its __syncthreads

    const int sub  = t & 15;             // m-sixteenth: [sub*64, sub*64+64)
    const int quad = t >> 4;             // 0..63: 2-row group within 128-row tile
    const int sbase16 = 129 * sub;       // SIDX(sub*64)

    // ---------------- phase 1: full mismatch, R=2 rows per thread ---------
    {
        float4 xa[2], xb[2];
        int rown[2];
        #pragma unroll
        for (int j = 0; j < 2; j++) {
            rown[j] = tile * 128 + quad * 2 + j;
            const float4* xr = (const float4*)(g_x0 + ((size_t)b * Nn + rown[j]) * Dn);
            xa[j] = xr[0]; xb[j] = xr[1];
        }
        float best[2] = {FLT_BIG, FLT_BIG};
        int bidx[2] = {-1, -1};
        #pragma unroll 4
        for (int i = 0; i < 64; i++) {
            float4 da = sdata[sbase16 + 2 * i];
            float4 db = sdata[sbase16 + 2 * i + 1];
            int m = sub * 64 + i;
            #pragma unroll
            for (int j = 0; j < 2; j++) {
                float acc = dist8(xa[j], xb[j], da, db);
                if (acc < best[j]) { best[j] = acc; bidx[j] = m; }  // strict <
            }
        }
        // merge the 16 m-sixteenths (width-16 shuffle); tie -> lower m
        #pragma unroll
        for (int off = 8; off >= 1; off >>= 1) {
            #pragma unroll
            for (int j = 0; j < 2; j++) {
                float ob = __shfl_down_sync(0xffffffffu, best[j], off, 16);
                int   oi = __shfl_down_sync(0xffffffffu, bidx[j], off, 16);
                if (ob < best[j] || (ob == best[j] && oi < bidx[j])) {
                    best[j] = ob; bidx[j] = oi;
                }
            }
        }
        if (sub == 0) {
            int nm = 0, mr[2];
            #pragma unroll
            for (int j = 0; j < 2; j++)
                if (bidx[j] != rown[j]) mr[nm++] = rown[j];
            if (nm) {
                int s = atomicAdd(&g_cnt[0][b], nm);
                for (int k = 0; k < nm; k++) g_lists[0][b][s + k] = mr[k];
            }
        }
    }
    gbar(1);

    // ---------------- phase 2: iterative renoise (smem tile reuse) --------
    // Unmasked rows invariant => only listed rows renoised + rechecked.
    const int wid = t >> 5;
    const int l   = t & 31;
    const int qd  = l >> 4;                // 0/1: which 2-row group in this warp
    const int wb  = (bid & 7) * 32 + wid;  // warp index within batch: 0..255
    for (int it = 0; it < MAXIT; it++) {
        int total = 0;
        #pragma unroll
        for (int i = 0; i < Bn; i++) total += g_cnt[it][i];
        if (total >= 10) {               // while-loop condition (global mask sum)
            const int cnt = g_cnt[it][b];
            const int* src = g_lists[it & 1][b];
            int*       dst = g_lists[(it + 1) & 1][b];
            const int ng = (cnt + 3) >> 2;          // 4 rows per warp-pass
            for (int g = wb; g < ng; g += 256) {
                int rn[2]; bool val[2];
                float4 xa[2], xb[2];
                #pragma unroll
                for (int j = 0; j < 2; j++) {
                    int li = g * 4 + qd * 2 + j;
                    val[j] = li < cnt;
                    rn[j] = val[j] ? src[li] : 0;
                    int rf = b * Nn + rn[j];
                    // x row = [data dims 0-2, noise_bank[it] dims 3-7]
                    float4 dA = ((const float4*)data)[(size_t)rf * 2];
                    const float4* np =
                        (const float4*)(noise_bank + ((size_t)it * NROWS + rf) * Dn);
                    float4 nA = np[0], nB = np[1];
                    xa[j] = make_float4(dA.x, dA.y, dA.z, nA.w);
                    xb[j] = nB;
                    if (sub == 0 && val[j]) {       // persist renoise for phase 3
                        g_x0[(size_t)rf * Dn + 3] = nA.w;
                        *((float4*)(g_x0 + (size_t)rf * Dn + 4)) = nB;
                    }
                }
                float best[2] = {FLT_BIG, FLT_BIG};
                int bidx[2] = {-1, -1};
                #pragma unroll 4
                for (int i = 0; i < 64; i++) {
                    float4 da = sdata[sbase16 + 2 * i];
                    float4 db = sdata[sbase16 + 2 * i + 1];
                    int m = sub * 64 + i;
                    #pragma unroll
                    for (int j = 0; j < 2; j++) {
                        float acc = dist8(xa[j], xb[j], da, db);
                        if (acc < best[j]) { best[j] = acc; bidx[j] = m; }
                    }
                }
                #pragma unroll
                for (int off = 8; off >= 1; off >>= 1) {
                    #pragma unroll
                    for (int j = 0; j < 2; j++) {
                        float ob = __shfl_down_sync(0xffffffffu, best[j], off, 16);
                        int   oi = __shfl_down_sync(0xffffffffu, bidx[j], off, 16);
                        if (ob < best[j] || (ob == best[j] && oi < bidx[j])) {
                            best[j] = ob; bidx[j] = oi;
                        }
                    }
                }
                if (sub == 0) {
                    int nm = 0, mr[2];
                    #pragma unroll
                    for (int j = 0; j < 2; j++)
                        if (val[j] && bidx[j] != rn[j]) mr[nm++] = rn[j];
                    if (nm) {
                        int s = atomicAdd(&g_cnt[it + 1][b], nm);
                        for (int k = 0; k < nm; k++) dst[s + k] = mr[k];
                    }
                }
            }
        }
        gbar(2 + it);
    }

    // ---------------- phase 3: fused model + masked loss ------------------
    {
        for (int i = t; i < Dn * Hn; i += TPB) sW1[i] = W1[i];
        for (int i = t; i < Hn * Dn; i += TPB) sW2[i] = W2[i];
        const float tb = tv[b];
        if (t < Hn)
            sbase[t] = g_cc[b * Hn + t] + tb * Wt[t] + b1[t];
        __syncthreads();

        const int q   = t & 7;            // h-octet: [q*32, q*32+32)
        const int r   = t >> 3;           // 0..127
        const int row = tile * 128 + r;
        const int base = (b * Nn + row) * Dn;

        float xt[Dn], ut[Dn], vt[Dn];
        #pragma unroll
        for (int d = 0; d < Dn; d++) {
            float dv = data[base + d];
            float xv = g_x0[base + d];
            ut[d] = dv - xv;
            xt[d] = (d < NCOND) ? dv : ((1.0f - tb) * xv + tb * dv);
            vt[d] = 0.f;
        }
        const int h0 = q * (Hn / 8);
        for (int h = h0; h < h0 + Hn / 8; h++) {
            float pre = sbase[h];
            #pragma unroll
            for (int d = 0; d < Dn; d++) pre = fmaf(xt[d], sW1[d * Hn + h], pre);
            float hh = tanhf(pre);
            #pragma unroll
            for (int d = 0; d < Dn; d++) vt[d] = fmaf(hh, sW2[h * Dn + d], vt[d]);
        }
        // merge h-octets (lanes 8r..8r+7)
        #pragma unroll
        for (int off = 4; off >= 1; off >>= 1) {
            #pragma unroll
            for (int d = 0; d < Dn; d++)
                vt[d] += __shfl_down_sync(0xffffffffu, vt[d], off, 8);
        }
        float part = 0.f;
        if (q == 0) {
            #pragma unroll
            for (int d = NCOND; d < Dn; d++) {
                float e = vt[d] - ut[d];
                part = fmaf(e, e, part);
            }
        }
        // deterministic warp reduction (fixed shuffle order)
        #pragma unroll
        for (int off = 16; off >= 1; off >>= 1)
            part += __shfl_down_sync(0xffffffffu, part, off);
        if (l == 0) swarp[wid] = part;
        __syncthreads();
        if (wid == 0) {
            float v = swarp[l];
            #pragma unroll
            for (int off = 16; off >= 1; off >>= 1)
                v += __shfl_down_sync(0xffffffffu, v, off);
            if (t == 0) g_partial[bid] = v;
        }
    }
    gbar(6);

    // ---------------- phase 4: per-batch deterministic sum ----------------
    if (bid == 0 && t < Bn) {
        float s = 0.f;
        #pragma unroll
        for (int i = 0; i < 8; i++) s += g_partial[t * 8 + i];
        out[t] = s / (float)(Nn * (Dn - NCOND));
    }
}

// ---------------- launch: ONE graph node ----------------------------------
extern "C" void kernel_launch(void* const* d_in, const int* in_sizes, int n_in,
                              void* d_out, int out_size) {
    const float* data = (const float*)d_in[0];
    const float* c    = (const float*)d_in[1];
    const float* t    = (const float*)d_in[2];
    const float* x0n  = (const float*)d_in[3];
    const float* nb   = (const float*)d_in[4];
    const float* W1   = (const float*)d_in[5];
    const float* Wc   = (const float*)d_in[6];
    const float* Wt   = (const float*)d_in[7];
    const float* b1   = (const float*)d_in[8];
    const float* W2   = (const float*)d_in[9];
    float* out = (float*)d_out;

    k_fused<<<GRID, TPB>>>(data, c, t, x0n, nb, W1, Wc, Wt, b1, W2, out);
}

// round 8
// speedup vs baseline: 1.1566x; 1.1566x over previous
#include <cuda_runtime.h>

#define Bn 16
#define Nn 1024
#define Dn 8
#define Cn 128
#define Hn 256
#define NCOND 3
#define MAXIT 4
#define NROWS (Bn * Nn)
#define GRID 128
#define TPB 512
#define FLT_BIG 3.402823466e38f

// ---------------- device scratch (no allocations allowed) ----------------
__device__ __align__(16) float g_x0[NROWS * Dn];   // 512 KB
__device__ float g_cc[Bn * Hn];
__device__ int g_cnt[MAXIT + 1][Bn];               // per-(pass, batch) masked count
__device__ int g_lists[2][Bn][Nn];                 // ping-pong per-batch masked row lists
__device__ float g_partial[GRID];
__device__ unsigned int g_barc[8];                 // monotonic barrier counters (never reset)

// Software grid barrier. GRID=128 blocks <= 148 SMs at occupancy 1 -> all
// co-resident; monotonic counters need no reset and are replay-deterministic.
__device__ __forceinline__ void gbar(int i) {
    __threadfence();
    __syncthreads();
    if (threadIdx.x == 0) {
        unsigned int old = atomicAdd(&g_barc[i], 1u);
        unsigned int target = (old & ~(unsigned int)(GRID - 1)) + (unsigned int)GRID;
        while (atomicAdd(&g_barc[i], 0u) < target) { __nanosleep(32); }
        __threadfence();
    }
    __syncthreads();
}

// squared distance, sequential d0..d7 accumulation (reference reduction order)
__device__ __forceinline__ float dist8(const float4 xa, const float4 xb,
                                       const float4 da, const float4 db) {
    float t0 = xa.x - da.x; float acc = t0 * t0;
    t0 = xa.y - da.y; acc = fmaf(t0, t0, acc);
    t0 = xa.z - da.z; acc = fmaf(t0, t0, acc);
    t0 = xa.w - da.w; acc = fmaf(t0, t0, acc);
    t0 = xb.x - db.x; acc = fmaf(t0, t0, acc);
    t0 = xb.y - db.y; acc = fmaf(t0, t0, acc);
    t0 = xb.z - db.z; acc = fmaf(t0, t0, acc);
    t0 = xb.w - db.w; acc = fmaf(t0, t0, acc);
    return acc;
}

// smem float4 index for data row m (pad 1 float4 per 32 rows). Lane l owns
// m = 32l + i -> idx = 65l + 2i; lane-octet bank-quads (l + 2i) mod 32 are
// all distinct -> conflict-free LDS.128.
#define SIDX(m) (2 * (m) + ((m) >> 5))

__global__ void __launch_bounds__(TPB, 1) k_fused(
    const float* __restrict__ data, const float* __restrict__ c,
    const float* __restrict__ tv,   const float* __restrict__ x0_noise,
    const float* __restrict__ noise_bank,
    const float* __restrict__ W1,   const float* __restrict__ Wc,
    const float* __restrict__ Wt,   const float* __restrict__ b1,
    const float* __restrict__ W2,   float* __restrict__ out) {

    // 33.3 KB tile (persists through phases 1-2), aliased by weights in phase 3
    __shared__ __align__(16) float smem_raw[(Nn * 2 + 32) * 4];
    __shared__ float sred[TPB];
    float4* sdata = (float4*)smem_raw;
    float*  sW1   = smem_raw;
    float*  sW2   = smem_raw + Dn * Hn;
    float*  sbase = smem_raw + 2 * Dn * Hn;

    const int t   = threadIdx.x;
    const int bid = blockIdx.x;
    const int gid = bid * TPB + t;
    const int b    = bid >> 3;           // batch owned by this block
    const int tile = bid & 7;
    const int lane = t & 31;
    const int wid  = t >> 5;             // 0..15

    // ---------------- phase 0: zero counters, init x0, cc = c @ Wc --------
    if (gid < (MAXIT + 1) * Bn) ((int*)g_cnt)[gid] = 0;
    for (int i = gid; i < NROWS * Dn; i += GRID * TPB) {
        int d = i & (Dn - 1);
        g_x0[i] = (d < NCOND) ? data[i] : x0_noise[i];
    }
    if (gid < Bn * Hn) {
        int bb = gid >> 8, h = gid & (Hn - 1);
        float acc = 0.f;
        #pragma unroll 8
        for (int j = 0; j < Cn; j++)
            acc = fmaf(c[bb * Cn + j], Wc[j * Hn + h], acc);
        g_cc[gid] = acc;
    }

    // ---------------- load data[b] tile into smem (padded) ----------------
    {
        const float4* dptr = (const float4*)(data + (size_t)b * Nn * Dn);
        for (int i = t; i < Nn * 2; i += TPB) {
            int m = i >> 1;
            sdata[SIDX(m) + (i & 1)] = dptr[i];
        }
    }
    gbar(0);   // also orders the smem tile via its __syncthreads

    const int sbase32 = 65 * lane;       // SIDX(lane*32)

    // ---------------- phase 1: full mismatch, 8 rows per warp -------------
    {
        float4 xa[8], xb[8];
        int rown[8];
        #pragma unroll
        for (int j = 0; j < 8; j++) {
            rown[j] = tile * 128 + wid * 8 + j;
            const float4* xr = (const float4*)(g_x0 + ((size_t)b * Nn + rown[j]) * Dn);
            xa[j] = xr[0]; xb[j] = xr[1];   // same addr all lanes -> broadcast
        }
        float best[8];
        int bidx[8];
        #pragma unroll
        for (int j = 0; j < 8; j++) { best[j] = FLT_BIG; bidx[j] = -1; }
        #pragma unroll 2
        for (int i = 0; i < 32; i++) {
            float4 da = sdata[sbase32 + 2 * i];
            float4 db = sdata[sbase32 + 2 * i + 1];
            int m = lane * 32 + i;
            #pragma unroll
            for (int j = 0; j < 8; j++) {
                float acc = dist8(xa[j], xb[j], da, db);
                if (acc < best[j]) { best[j] = acc; bidx[j] = m; }  // strict <
            }
        }
        // full-warp merge; lane order == m order; tie -> lower m (first index)
        #pragma unroll
        for (int off = 16; off >= 1; off >>= 1) {
            #pragma unroll
            for (int j = 0; j < 8; j++) {
                float ob = __shfl_down_sync(0xffffffffu, best[j], off);
                int   oi = __shfl_down_sync(0xffffffffu, bidx[j], off);
                if (ob < best[j] || (ob == best[j] && oi < bidx[j])) {
                    best[j] = ob; bidx[j] = oi;
                }
            }
        }
        if (lane == 0) {
            int nm = 0, mr[8];
            #pragma unroll
            for (int j = 0; j < 8; j++)
                if (bidx[j] != rown[j]) mr[nm++] = rown[j];
            if (nm) {
                int s = atomicAdd(&g_cnt[0][b], nm);
                for (int k = 0; k < nm; k++) g_lists[0][b][s + k] = mr[k];
            }
        }
    }
    gbar(1);

    // ---------------- phase 2: iterative renoise (smem tile reuse) --------
    // Unmasked rows invariant => only listed rows renoised + rechecked.
    const int wb = (bid & 7) * 16 + wid;   // warp index within batch: 0..127
    for (int it = 0; it < MAXIT; it++) {
        int total = 0;
        #pragma unroll
        for (int i = 0; i < Bn; i++) total += g_cnt[it][i];
        if (total >= 10) {               // while-loop condition (global mask sum)
            const int cnt = g_cnt[it][b];
            const int* src = g_lists[it & 1][b];
            int*       dst = g_lists[(it + 1) & 1][b];
            const int ng = (cnt + 7) >> 3;          // 8 rows per warp-pass
            for (int g = wb; g < ng; g += 128) {
                int rn[8]; bool val[8];
                float4 xa[8], xb[8];
                #pragma unroll
                for (int j = 0; j < 8; j++) {
                    int li = g * 8 + j;
                    val[j] = li < cnt;
                    rn[j] = val[j] ? src[li] : 0;
                    int rf = b * Nn + rn[j];
                    // x row = [data dims 0-2, noise_bank[it] dims 3-7]
                    float4 dA = ((const float4*)data)[(size_t)rf * 2];
                    const float4* np =
                        (const float4*)(noise_bank + ((size_t)it * NROWS + rf) * Dn);
                    float4 nA = np[0], nB = np[1];
                    xa[j] = make_float4(dA.x, dA.y, dA.z, nA.w);
                    xb[j] = nB;
                    if (lane == 0 && val[j]) {       // persist renoise for phase 3
                        g_x0[(size_t)rf * Dn + 3] = nA.w;
                        *((float4*)(g_x0 + (size_t)rf * Dn + 4)) = nB;
                    }
                }
                float best[8];
                int bidx[8];
                #pragma unroll
                for (int j = 0; j < 8; j++) { best[j] = FLT_BIG; bidx[j] = -1; }
                #pragma unroll 2
                for (int i = 0; i < 32; i++) {
                    float4 da = sdata[sbase32 + 2 * i];
                    float4 db = sdata[sbase32 + 2 * i + 1];
                    int m = lane * 32 + i;
                    #pragma unroll
                    for (int j = 0; j < 8; j++) {
                        float acc = dist8(xa[j], xb[j], da, db);
                        if (acc < best[j]) { best[j] = acc; bidx[j] = m; }
                    }
                }
                #pragma unroll
                for (int off = 16; off >= 1; off >>= 1) {
                    #pragma unroll
                    for (int j = 0; j < 8; j++) {
                        float ob = __shfl_down_sync(0xffffffffu, best[j], off);
                        int   oi = __shfl_down_sync(0xffffffffu, bidx[j], off);
                        if (ob < best[j] || (ob == best[j] && oi < bidx[j])) {
                            best[j] = ob; bidx[j] = oi;
                        }
                    }
                }
                if (lane == 0) {
                    int nm = 0, mr[8];
                    #pragma unroll
                    for (int j = 0; j < 8; j++)
                        if (val[j] && bidx[j] != rn[j]) mr[nm++] = rn[j];
                    if (nm) {
                        int s = atomicAdd(&g_cnt[it + 1][b], nm);
                        for (int k = 0; k < nm; k++) dst[s + k] = mr[k];
                    }
                }
            }
        }
        gbar(2 + it);
    }

    // ---------------- phase 3: fused model + masked loss ------------------
    {
        for (int i = t; i < Dn * Hn; i += TPB) sW1[i] = W1[i];
        for (int i = t; i < Hn * Dn; i += TPB) sW2[i] = W2[i];
        const float tb = tv[b];
        if (t < Hn)
            sbase[t] = g_cc[b * Hn + t] + tb * Wt[t] + b1[t];
        __syncthreads();

        const int q   = t & 3;            // h-quarter: [q*64, q*64+64)
        const int r   = t >> 2;           // 0..127
        const int row = tile * 128 + r;
        const int base = (b * Nn + row) * Dn;

        float xt[Dn], ut[Dn], vt[Dn];
        #pragma unroll
        for (int d = 0; d < Dn; d++) {
            float dv = data[base + d];
            float xv = g_x0[base + d];
            ut[d] = dv - xv;
            xt[d] = (d < NCOND) ? dv : ((1.0f - tb) * xv + tb * dv);
            vt[d] = 0.f;
        }
        const int h0 = q * (Hn / 4);
        for (int h = h0; h < h0 + Hn / 4; h++) {
            float pre = sbase[h];
            #pragma unroll
            for (int d = 0; d < Dn; d++) pre = fmaf(xt[d], sW1[d * Hn + h], pre);
            float hh = tanhf(pre);
            #pragma unroll
            for (int d = 0; d < Dn; d++) vt[d] = fmaf(hh, sW2[h * Dn + d], vt[d]);
        }
        // merge h-quarters (lanes 4r..4r+3)
        #pragma unroll
        for (int off = 2; off >= 1; off >>= 1) {
            #pragma unroll
            for (int d = 0; d < Dn; d++)
                vt[d] += __shfl_down_sync(0xffffffffu, vt[d], off, 4);
        }
        float part = 0.f;
        if (q == 0) {
            #pragma unroll
            for (int d = NCOND; d < Dn; d++) {
                float e = vt[d] - ut[d];
                part = fmaf(e, e, part);
            }
        }
        sred[t] = part;
        __syncthreads();
        // deterministic tree reduction
        for (int s = TPB / 2; s > 0; s >>= 1) {
            if (t < s) sred[t] += sred[t + s];
            __syncthreads();
        }
        if (t == 0) g_partial[bid] = sred[0];
    }
    gbar(6);

    // ---------------- phase 4: per-batch deterministic sum ----------------
    if (bid == 0 && t < Bn) {
        float s = 0.f;
        #pragma unroll
        for (int i = 0; i < 8; i++) s += g_partial[t * 8 + i];
        out[t] = s / (float)(Nn * (Dn - NCOND));
    }
}

// ---------------- launch: ONE graph node ----------------------------------
extern "C" void kernel_launch(void* const* d_in, const int* in_sizes, int n_in,
                              void* d_out, int out_size) {
    const float* data = (const float*)d_in[0];
    const float* c    = (const float*)d_in[1];
    const float* t    = (const float*)d_in[2];
    const float* x0n  = (const float*)d_in[3];
    const float* nb   = (const float*)d_in[4];
    const float* W1   = (const float*)d_in[5];
    const float* Wc   = (const float*)d_in[6];
    const float* Wt   = (const float*)d_in[7];
    const float* b1   = (const float*)d_in[8];
    const float* W2   = (const float*)d_in[9];
    float* out = (float*)d_out;

    k_fused<<<GRID, TPB>>>(data, c, t, x0n, nb, W1, Wc, Wt, b1, W2, out);
}